// round 16
// baseline (speedup 1.0000x reference)
#include <cuda_runtime.h>
#include <cuda_bf16.h>
#include <cstdint>

// ---------------------------------------------------------------------------
// Problem constants
// ---------------------------------------------------------------------------
#define BQ    4096
#define SRCM1 49
#define TGTQ  25
#define RQ    1024
#define HQ    67
#define IQ    82

// ---------------------------------------------------------------------------
// fp32 scratch
// ---------------------------------------------------------------------------
constexpr long long OFF_HCAT = 0;                                   // [BQ, 2R]
constexpr long long OFF_GI1  = OFF_HCAT + (long long)BQ * 2 * RQ;   // [BQ, 3R] decoder
constexpr long long OFF_GH1  = OFF_GI1  + (long long)BQ * 3 * RQ;
constexpr long long OFF_GI2  = OFF_GH1  + (long long)BQ * 3 * RQ;
constexpr long long OFF_GH2  = OFF_GI2  + (long long)BQ * 3 * RQ;
constexpr long long OFF_GIALL= OFF_GH2  + (long long)BQ * 3 * RQ;   // [BQ*49, 3R]
constexpr long long SCRATCH_TOTAL = OFF_GIALL + (long long)BQ * SRCM1 * 3 * RQ;

__device__ float g_scratch[SCRATCH_TOTAL];

// ---------------------------------------------------------------------------
// bf16 split scratch
// ---------------------------------------------------------------------------
constexpr long long NW = 3LL * RQ * RQ;
constexpr long long OFFB_W1H = 0;                       // Wh1
constexpr long long OFFB_W1L = OFFB_W1H + NW;
constexpr long long OFFB_W2H = OFFB_W1L + NW;           // Wi2
constexpr long long OFFB_W2L = OFFB_W2H + NW;
constexpr long long OFFB_W3H = OFFB_W2L + NW;           // Wh2
constexpr long long OFFB_W3L = OFFB_W3H + NW;
constexpr long long OFFB_HH  = OFFB_W3L + NW;           // hcat hi [BQ][2R]
constexpr long long OFFB_HL  = OFFB_HH + (long long)BQ * 2 * RQ;
constexpr long long BF_TOTAL = OFFB_HL + (long long)BQ * 2 * RQ;

__device__ __nv_bfloat16 g_bf[BF_TOTAL];

// ---------------------------------------------------------------------------
// Common helpers
// ---------------------------------------------------------------------------
__device__ __forceinline__ uint32_t smem_u32(const void* p) {
    uint32_t a;
    asm("{ .reg .u64 t; cvta.to.shared.u64 t, %1; cvt.u32.u64 %0, t; }"
        : "=r"(a) : "l"(p));
    return a;
}

#define MMA_BF16(ACC, A0, A1, A2, A3, B0, B1)                                  \
    asm volatile(                                                              \
        "mma.sync.aligned.m16n8k16.row.col.f32.bf16.bf16.f32 "                 \
        "{%0,%1,%2,%3}, {%4,%5,%6,%7}, {%8,%9}, {%0,%1,%2,%3};"                \
        : "+f"((ACC)[0]), "+f"((ACC)[1]), "+f"((ACC)[2]), "+f"((ACC)[3])       \
        : "r"(A0), "r"(A1), "r"(A2), "r"(A3), "r"(B0), "r"(B1))

#define LDM_X4(R0, R1, R2, R3, ADDR)                                           \
    asm volatile(                                                              \
        "ldmatrix.sync.aligned.m8n8.x4.shared.b16 {%0,%1,%2,%3}, [%4];"        \
        : "=r"(R0), "=r"(R1), "=r"(R2), "=r"(R3) : "r"(ADDR))

__device__ __forceinline__ void cp16(uint32_t dst, const void* src) {
    asm volatile("cp.async.ca.shared.global [%0], [%1], 16;"
                 :: "r"(dst), "l"(src));
}
#define CP_COMMIT() asm volatile("cp.async.commit_group;" ::: "memory")
#define CP_WAIT2()  asm volatile("cp.async.wait_group 2;" ::: "memory")

// Swizzled smem offset inside a 128x16(bf16) tile: row r, 16B-half h.
__device__ __forceinline__ uint32_t swz(int r, int h) {
    return (uint32_t)(((r >> 2) << 7) + ((r & 3) << 5) + ((h ^ ((r >> 2) & 1)) << 4));
}

// ---------------------------------------------------------------------------
// Big GEMM (bf16x3, legacy HMMA):  C[4096, 3072] = A[4096,1024] @ W[3072,1024]^T
//   R7 mainloop body, ring deepened to 4 stages x 16KB (64KB dynamic smem),
//   wait_group 2 -> 3 fills in flight for DRAM-tail latency cover.
//   128x128 block, 8 warps (2M x 4N), occupancy 2 (128KB smem/SM).
//   gridDim.z selects one of THREE fused independent GEMMs
//   (gi2_s, gh2_s, gh1_{s+1}) — merged launch backfills wave tails.
// ---------------------------------------------------------------------------
#define GLDA (2 * RQ)     // 2048
#define GLDC (3 * RQ)     // 3072
#define GKIT 64           // K / 16
#define STG  4
#define SMEM_BIG (STG * 16384)   // 65536

__global__ __launch_bounds__(256, 2)
void gemm_big3_kernel(long long ah0, long long al0, long long wh0, long long wl0,
                      const float* __restrict__ b0, long long c0,
                      long long ah1, long long al1, long long wh1, long long wl1,
                      const float* __restrict__ b1, long long c1,
                      long long ah2, long long al2, long long wh2, long long wl2,
                      const float* __restrict__ b2, long long c2)
{
    extern __shared__ __align__(128) uint8_t sm[];
    const uint32_t sbase = smem_u32(sm);

    const int z = blockIdx.z;
    const long long ah = (z == 0) ? ah0 : (z == 1) ? ah1 : ah2;
    const long long al = (z == 0) ? al0 : (z == 1) ? al1 : al2;
    const long long wh = (z == 0) ? wh0 : (z == 1) ? wh1 : wh2;
    const long long wl = (z == 0) ? wl0 : (z == 1) ? wl1 : wl2;
    const float* bias  = (z == 0) ? b0  : (z == 1) ? b1  : b2;
    const long long co = (z == 0) ? c0  : (z == 1) ? c1  : c2;

    const __nv_bfloat16* AH = g_bf + ah;
    const __nv_bfloat16* AL = g_bf + al;
    const __nv_bfloat16* WH = g_bf + wh;
    const __nv_bfloat16* WL = g_bf + wl;
    float* C = g_scratch + co;

    const int tid  = threadIdx.x;
    const int lane = tid & 31;
    const int warp = tid >> 5;
    const int wm   = (warp >> 2) * 64;
    const int wn   = (warp & 3) * 32;
    const int bm   = blockIdx.y * 128;
    const int bn   = blockIdx.x * 128;

    // fill coords: row 0..127, 16B half
    const int fr = (tid >> 1) & 127;
    const int fh = tid & 1;
    const uint32_t fd = swz(fr, fh);
    const __nv_bfloat16* pAH = AH + (size_t)(bm + fr) * GLDA + fh * 8;
    const __nv_bfloat16* pAL = AL + (size_t)(bm + fr) * GLDA + fh * 8;
    const __nv_bfloat16* pWH = WH + (size_t)(bn + fr) * RQ + fh * 8;
    const __nv_bfloat16* pWL = WL + (size_t)(bn + fr) * RQ + fh * 8;

    // fragment smem offsets (lane-fixed)
    const int mrow = lane & 15;
    const int akh  = (lane >> 4) & 1;
    uint32_t aoff[4];
#pragma unroll
    for (int mt = 0; mt < 4; mt++) aoff[mt] = swz(wm + mt * 16 + mrow, akh);
    const int nrow = wn + (lane & 7) + ((lane >> 4) & 1) * 8;
    const int bkh  = (lane >> 3) & 1;
    uint32_t boff[2];
#pragma unroll
    for (int p = 0; p < 2; p++) boff[p] = swz(nrow + p * 16, bkh);

    float acc[4][4][4];
#pragma unroll
    for (int mt = 0; mt < 4; mt++)
#pragma unroll
        for (int nt = 0; nt < 4; nt++)
#pragma unroll
            for (int q = 0; q < 4; q++) acc[mt][nt][q] = 0.0f;

    auto fill = [&](int it) {
        if (it < GKIT) {
            const uint32_t bb = sbase + (it % STG) * 16384;
            const int k = it * 16;
            cp16(bb + fd,         pAH + k);
            cp16(bb + 4096 + fd,  pAL + k);
            cp16(bb + 8192 + fd,  pWH + k);
            cp16(bb + 12288 + fd, pWL + k);
        }
        CP_COMMIT();
    };

    fill(0);
    fill(1);
    fill(2);

    for (int it = 0; it < GKIT; it++) {
        CP_WAIT2();            // stage it ready (<=2 pending: it+1, it+2)
        __syncthreads();
        fill(it + 3);          // overwrites stage (it-1)%4: consumed last iter

        const uint32_t bufb = sbase + (it % STG) * 16384;

        uint32_t bfH[4][2], bfL[4][2];
#pragma unroll
        for (int p = 0; p < 2; p++) {
            uint32_t r0, r1, r2, r3;
            LDM_X4(r0, r1, r2, r3, bufb + 8192 + boff[p]);
            bfH[2 * p][0] = r0; bfH[2 * p][1] = r1;
            bfH[2 * p + 1][0] = r2; bfH[2 * p + 1][1] = r3;
            LDM_X4(r0, r1, r2, r3, bufb + 12288 + boff[p]);
            bfL[2 * p][0] = r0; bfL[2 * p][1] = r1;
            bfL[2 * p + 1][0] = r2; bfL[2 * p + 1][1] = r3;
        }

#pragma unroll
        for (int mt = 0; mt < 4; mt++) {
            uint32_t aH[4], aL[4];
            LDM_X4(aH[0], aH[1], aH[2], aH[3], bufb + aoff[mt]);
            LDM_X4(aL[0], aL[1], aL[2], aL[3], bufb + 4096 + aoff[mt]);
#pragma unroll
            for (int nt = 0; nt < 4; nt++)
                MMA_BF16(acc[mt][nt], aL[0], aL[1], aL[2], aL[3],
                         bfH[nt][0], bfH[nt][1]);
#pragma unroll
            for (int nt = 0; nt < 4; nt++)
                MMA_BF16(acc[mt][nt], aH[0], aH[1], aH[2], aH[3],
                         bfL[nt][0], bfL[nt][1]);
#pragma unroll
            for (int nt = 0; nt < 4; nt++)
                MMA_BF16(acc[mt][nt], aH[0], aH[1], aH[2], aH[3],
                         bfH[nt][0], bfH[nt][1]);
        }
    }

    // epilogue: bias, float2 stores
#pragma unroll
    for (int mt = 0; mt < 4; mt++) {
#pragma unroll
        for (int nt = 0; nt < 4; nt++) {
            const int n = bn + wn + nt * 8 + 2 * (lane & 3);
            const float b0v = bias[n], b1v = bias[n + 1];
#pragma unroll
            for (int h = 0; h < 2; h++) {
                const int m = bm + wm + mt * 16 + (lane >> 2) + h * 8;
                float2 v;
                v.x = acc[mt][nt][h * 2 + 0] + b0v;
                v.y = acc[mt][nt][h * 2 + 1] + b1v;
                *(float2*)(C + (size_t)m * GLDC + n) = v;
            }
        }
    }
}

// ---------------------------------------------------------------------------
// Legacy bf16x3 mma.sync GEMM (fp32 inputs): K=82 input GEMMs and N=67 FC.
//   xt >= 0: A is the decoder input x_t gathered on the fly.
//   resExt: external residual base (row stride res_ld) when Roff < 0.
// ---------------------------------------------------------------------------
#define BM 128
#define BN 64
#define BK 32

__device__ __forceinline__ void split2(float x, float y, uint32_t& hi, uint32_t& lo)
{
    __nv_bfloat162 h = __floats2bfloat162_rn(x, y);
    float xr = x - __bfloat162float(__low2bfloat16(h));
    float yr = y - __bfloat162float(__high2bfloat16(h));
    __nv_bfloat162 l = __floats2bfloat162_rn(xr, yr);
    hi = *reinterpret_cast<uint32_t*>(&h);
    lo = *reinterpret_cast<uint32_t*>(&l);
}

__global__ __launch_bounds__(256, 2)
void gemm_bf16x3_kernel(const float* __restrict__ Aext, long long Aoff, int lda,
                        const float* __restrict__ W,
                        const float* __restrict__ bias,
                        const float* __restrict__ resExt, long long Roff, int res_ld,
                        float* __restrict__ Cext, long long Coff, int ldc,
                        int N, int K,
                        const float* __restrict__ decP,
                        const float* __restrict__ outP, int xt)
{
    const float* A = (Aoff >= 0) ? (g_scratch + Aoff) : Aext;
    float*       C = (Coff >= 0) ? (g_scratch + Coff) : Cext;
    const float* res = (Roff >= 0) ? (g_scratch + Roff) : resExt;

    __shared__ uint32_t AsH[BK / 2][BM + 8];
    __shared__ uint32_t AsL[BK / 2][BM + 8];
    __shared__ uint32_t BsH[BK / 2][BN + 8];
    __shared__ uint32_t BsL[BK / 2][BN + 8];

    const int tid  = threadIdx.x;
    const int bm   = blockIdx.y * BM;
    const int bn   = blockIdx.x * BN;
    const int arow = tid >> 1;
    const int akh  = (tid & 1) * 16;
    const int wrow = tid >> 2;
    const int wkq  = (tid & 3) * 8;
    const int lane = tid & 31;
    const int warp = tid >> 5;
    const int wm   = (warp >> 1) * 32;
    const int wn   = (warp & 1) * 32;
    const int gid  = lane >> 2;
    const int tig  = lane & 3;

    const bool fast   = (xt < 0) && ((K & (BK - 1)) == 0) && ((lda & 3) == 0);
    const int  ktiles = (K + BK - 1) / BK;

    float acc[2][4][4];
#pragma unroll
    for (int mt = 0; mt < 2; mt++)
#pragma unroll
        for (int nt = 0; nt < 4; nt++)
#pragma unroll
            for (int q = 0; q < 4; q++) acc[mt][nt][q] = 0.0f;

    for (int kt = 0; kt < ktiles; kt++) {
        const int k0 = kt * BK;
        __syncthreads();

        float av[16];
        if (fast) {
#pragma unroll
            for (int q = 0; q < 4; q++) {
                const float4 v = *reinterpret_cast<const float4*>(
                    A + (size_t)(bm + arow) * lda + k0 + akh + q * 4);
                av[q * 4 + 0] = v.x; av[q * 4 + 1] = v.y;
                av[q * 4 + 2] = v.z; av[q * 4 + 3] = v.w;
            }
        } else if (xt >= 0) {
            // on-the-fly decoder input gather (replaces build_x + X buffer)
            const int m = bm + arow;
#pragma unroll
            for (int j = 0; j < 16; j++) {
                const int k = k0 + akh + j;
                float v = 0.0f;
                if (k < K) {
                    if (xt == 0)
                        v = decP[(size_t)m * TGTQ * IQ + k];
                    else if (k < HQ)
                        v = outP[((size_t)m * TGTQ + (xt - 1)) * HQ + k];
                    else
                        v = decP[((size_t)m * TGTQ + xt) * IQ + k];
                }
                av[j] = v;
            }
        } else {
#pragma unroll
            for (int j = 0; j < 16; j++) {
                const int k = k0 + akh + j;
                av[j] = (k < K) ? A[(size_t)(bm + arow) * lda + k] : 0.0f;
            }
        }
#pragma unroll
        for (int j = 0; j < 8; j++) {
            uint32_t hi, lo;
            split2(av[2 * j], av[2 * j + 1], hi, lo);
            AsH[akh / 2 + j][arow] = hi;
            AsL[akh / 2 + j][arow] = lo;
        }

        float wv[8];
        if (((K & (BK - 1)) == 0) && (bn + wrow) < N) {
#pragma unroll
            for (int q = 0; q < 2; q++) {
                const float4 v = *reinterpret_cast<const float4*>(
                    W + (size_t)(bn + wrow) * K + k0 + wkq + q * 4);
                wv[q * 4 + 0] = v.x; wv[q * 4 + 1] = v.y;
                wv[q * 4 + 2] = v.z; wv[q * 4 + 3] = v.w;
            }
        } else {
#pragma unroll
            for (int j = 0; j < 8; j++) {
                const int k = k0 + wkq + j;
                wv[j] = (k < K && (bn + wrow) < N)
                    ? W[(size_t)(bn + wrow) * K + k] : 0.0f;
            }
        }
#pragma unroll
        for (int j = 0; j < 4; j++) {
            uint32_t hi, lo;
            split2(wv[2 * j], wv[2 * j + 1], hi, lo);
            BsH[wkq / 2 + j][wrow] = hi;
            BsL[wkq / 2 + j][wrow] = lo;
        }
        __syncthreads();

#pragma unroll
        for (int kc = 0; kc < 2; kc++) {
            const int kb = kc * 8;
            uint32_t afH[2][4], afL[2][4], bfH[4][2], bfL[4][2];
#pragma unroll
            for (int mt = 0; mt < 2; mt++) {
                const int r0 = wm + mt * 16 + gid;
                afH[mt][0] = AsH[kb + tig][r0];
                afH[mt][1] = AsH[kb + tig][r0 + 8];
                afH[mt][2] = AsH[kb + tig + 4][r0];
                afH[mt][3] = AsH[kb + tig + 4][r0 + 8];
                afL[mt][0] = AsL[kb + tig][r0];
                afL[mt][1] = AsL[kb + tig][r0 + 8];
                afL[mt][2] = AsL[kb + tig + 4][r0];
                afL[mt][3] = AsL[kb + tig + 4][r0 + 8];
            }
#pragma unroll
            for (int nt = 0; nt < 4; nt++) {
                const int c0 = wn + nt * 8 + gid;
                bfH[nt][0] = BsH[kb + tig][c0];
                bfH[nt][1] = BsH[kb + tig + 4][c0];
                bfL[nt][0] = BsL[kb + tig][c0];
                bfL[nt][1] = BsL[kb + tig + 4][c0];
            }
#pragma unroll
            for (int mt = 0; mt < 2; mt++)
#pragma unroll
                for (int nt = 0; nt < 4; nt++) {
                    MMA_BF16(acc[mt][nt],
                             afL[mt][0], afL[mt][1], afL[mt][2], afL[mt][3],
                             bfH[nt][0], bfH[nt][1]);
                    MMA_BF16(acc[mt][nt],
                             afH[mt][0], afH[mt][1], afH[mt][2], afH[mt][3],
                             bfL[nt][0], bfL[nt][1]);
                    MMA_BF16(acc[mt][nt],
                             afH[mt][0], afH[mt][1], afH[mt][2], afH[mt][3],
                             bfH[nt][0], bfH[nt][1]);
                }
        }
    }

#pragma unroll
    for (int mt = 0; mt < 2; mt++) {
#pragma unroll
        for (int nt = 0; nt < 4; nt++) {
            const int m0 = bm + wm + mt * 16 + gid;
            const int n0 = bn + wn + nt * 8 + 2 * tig;
#pragma unroll
            for (int h = 0; h < 2; h++) {
                const int m = m0 + h * 8;
#pragma unroll
                for (int q = 0; q < 2; q++) {
                    const int n = n0 + q;
                    if (n < N) {
                        float v = acc[mt][nt][h * 2 + q] + bias[n];
                        if (res) v += res[(size_t)m * res_ld + n];
                        C[(size_t)m * ldc + n] = v;
                    }
                }
            }
        }
    }
}

// ---------------------------------------------------------------------------
// GRU combine (vectorized x4): h_new = (1-z)*n + z*h, plus bf16 hi/lo splits.
// ---------------------------------------------------------------------------
__global__ void gru_combine_kernel(long long gi_off, int gi_rstride, int gi_roff,
                                   long long gh_off, long long h_off, long long hb)
{
    const int idx4 = blockIdx.x * blockDim.x + threadIdx.x;
    if (idx4 >= BQ * RQ / 4) return;
    const int b  = idx4 >> 8;            // / (RQ/4)
    const int j4 = (idx4 & 255) * 4;

    const float* gi = g_scratch + gi_off;
    const float* gh = g_scratch + gh_off;
    float*       h  = g_scratch + h_off;

    const size_t gr = ((size_t)b * gi_rstride + gi_roff) * (3 * RQ) + j4;
    const float4 ir4 = *(const float4*)(gi + gr);
    const float4 iz4 = *(const float4*)(gi + gr + RQ);
    const float4 in4 = *(const float4*)(gi + gr + 2 * RQ);

    const size_t g = (size_t)b * 3 * RQ + j4;
    const float4 hr4 = *(const float4*)(gh + g);
    const float4 hz4 = *(const float4*)(gh + g + RQ);
    const float4 hn4 = *(const float4*)(gh + g + 2 * RQ);

    const size_t hi = (size_t)b * 2 * RQ + j4;
    const float4 hp4 = *(const float4*)(h + hi);

    const float ir[4] = {ir4.x, ir4.y, ir4.z, ir4.w};
    const float iz[4] = {iz4.x, iz4.y, iz4.z, iz4.w};
    const float in_[4] = {in4.x, in4.y, in4.z, in4.w};
    const float hr[4] = {hr4.x, hr4.y, hr4.z, hr4.w};
    const float hz[4] = {hz4.x, hz4.y, hz4.z, hz4.w};
    const float hn[4] = {hn4.x, hn4.y, hn4.z, hn4.w};
    const float hp[4] = {hp4.x, hp4.y, hp4.z, hp4.w};

    float v[4];
    __nv_bfloat16 vh[4], vl[4];
#pragma unroll
    for (int q = 0; q < 4; q++) {
        const float r = 1.0f / (1.0f + expf(-(ir[q] + hr[q])));
        const float z = 1.0f / (1.0f + expf(-(iz[q] + hz[q])));
        const float n = tanhf(in_[q] + r * hn[q]);
        v[q] = (1.0f - z) * n + z * hp[q];
        vh[q] = __float2bfloat16(v[q]);
        vl[q] = __float2bfloat16(v[q] - __bfloat162float(vh[q]));
    }

    *(float4*)(h + hi) = make_float4(v[0], v[1], v[2], v[3]);

    const size_t bo = (size_t)b * 2 * RQ + hb + j4;
    __nv_bfloat162* pH = (__nv_bfloat162*)(g_bf + OFFB_HH + bo);
    __nv_bfloat162* pL = (__nv_bfloat162*)(g_bf + OFFB_HL + bo);
    pH[0] = __nv_bfloat162(vh[0], vh[1]);
    pH[1] = __nv_bfloat162(vh[2], vh[3]);
    pL[0] = __nv_bfloat162(vl[0], vl[1]);
    pL[1] = __nv_bfloat162(vl[2], vl[3]);
}

// ---------------------------------------------------------------------------
// Weight split, zero fills
// ---------------------------------------------------------------------------
__global__ void split_w_kernel(const float* __restrict__ W,
                               long long dh, long long dl, int count)
{
    const int i = blockIdx.x * blockDim.x + threadIdx.x;
    if (i >= count) return;
    const float v = W[i];
    const __nv_bfloat16 h = __float2bfloat16(v);
    g_bf[dh + i] = h;
    g_bf[dl + i] = __float2bfloat16(v - __bfloat162float(h));
}

__global__ void zero_kernel(long long off, long long count)
{
    const long long idx = (long long)blockIdx.x * blockDim.x + threadIdx.x;
    if (idx < count) g_scratch[off + idx] = 0.0f;
}

__global__ void zero_bf_kernel(long long off, long long count)
{
    const long long idx = (long long)blockIdx.x * blockDim.x + threadIdx.x;
    if (idx < count) g_bf[off + idx] = __float2bfloat16(0.0f);
}

// ---------------------------------------------------------------------------
// Launch
// ---------------------------------------------------------------------------
extern "C" void kernel_launch(void* const* d_in, const int* in_sizes, int n_in,
                              void* d_out, int out_size)
{
    const float* enc = (const float*)d_in[0];
    const float* dec = (const float*)d_in[1];
    const float* Wi1 = (const float*)d_in[2];
    const float* Wh1 = (const float*)d_in[3];
    const float* bi1 = (const float*)d_in[4];
    const float* bh1 = (const float*)d_in[5];
    const float* Wi2 = (const float*)d_in[6];
    const float* Wh2 = (const float*)d_in[7];
    const float* bi2 = (const float*)d_in[8];
    const float* bh2 = (const float*)d_in[9];
    const float* Wfc = (const float*)d_in[10];
    const float* bfc = (const float*)d_in[11];
    float* out = (float*)d_out;
    (void)in_sizes; (void)n_in; (void)out_size;

    // 64KB dynamic smem for the ring (idempotent, capture-safe)
    cudaFuncSetAttribute((const void*)gemm_big3_kernel,
                         cudaFuncAttributeMaxDynamicSharedMemorySize, SMEM_BIG);

    const dim3 blk(256);
    const dim3 gridZ1(GLDC / 128, BQ / 128, 1);            // (24, 32, 1)
    const dim3 gridZ2(GLDC / 128, BQ / 128, 2);            // (24, 32, 2)
    const dim3 gridZ3(GLDC / 128, BQ / 128, 3);            // (24, 32, 3)
    const dim3 grid3R((3 * RQ) / BN, BQ / BM);             // (48, 32)
    const dim3 gridEnc((3 * RQ) / BN, (BQ * SRCM1) / BM);  // (48, 1568)
    const dim3 gridFC((HQ + BN - 1) / BN, BQ / BM);        // (2, 32)
    const int  combine_blocks = (BQ * RQ / 4) / 256;       // 4096
    const int  wsplit_blocks = (int)((NW + 255) / 256);

    // per-launch init: zero h (fp32 + splits), split weights
    zero_kernel<<<(int)((BQ * 2LL * RQ + 255) / 256), blk>>>(OFF_HCAT, (long long)BQ * 2 * RQ);
    zero_bf_kernel<<<(int)((2LL * BQ * 2 * RQ + 255) / 256), blk>>>(OFFB_HH, 2LL * BQ * 2 * RQ);
    split_w_kernel<<<wsplit_blocks, blk>>>(Wh1, OFFB_W1H, OFFB_W1L, (int)NW);
    split_w_kernel<<<wsplit_blocks, blk>>>(Wi2, OFFB_W2H, OFFB_W2L, (int)NW);
    split_w_kernel<<<wsplit_blocks, blk>>>(Wh2, OFFB_W3H, OFFB_W3L, (int)NW);

    // batched encoder gi1: enc flattened row-major [BQ*49, IQ], row m = b*49+t
    gemm_bf16x3_kernel<<<gridEnc, blk>>>(enc, -1, IQ,
                                         Wi1, bi1,
                                         nullptr, -1, 0,
                                         nullptr, OFF_GIALL, 3 * RQ, 3 * RQ, IQ,
                                         nullptr, nullptr, -1);

    // prologue: gh1 for step 0 (h1 = 0 -> GEMM on zero splits gives bh1)
    gemm_big3_kernel<<<gridZ1, blk, SMEM_BIG>>>(
        OFFB_HH, OFFB_HL, OFFB_W1H, OFFB_W1L, bh1, OFF_GH1,
        0, 0, 0, 0, nullptr, 0,
        0, 0, 0, 0, nullptr, 0);

    const int NSTEPS = SRCM1 + TGTQ;    // 74
    for (int s = 0; s < NSTEPS; s++) {
        const bool is_dec = (s >= SRCM1);
        const int t = is_dec ? (s - SRCM1) : s;

        if (is_dec) {
            // gi1 with fused on-the-fly input gather (no build_x, no X buffer)
            gemm_bf16x3_kernel<<<grid3R, blk>>>(nullptr, -1, 0,
                                                Wi1, bi1,
                                                nullptr, -1, 0,
                                                nullptr, OFF_GI1, 3 * RQ, 3 * RQ, IQ,
                                                dec, out, t);
        }

        // combine1: h1_s from gi1_s + gh1_s (gh1 written by previous z launch)
        if (is_dec)
            gru_combine_kernel<<<combine_blocks, blk>>>(OFF_GI1, 1, 0,
                                                        OFF_GH1, OFF_HCAT, 0);
        else
            gru_combine_kernel<<<combine_blocks, blk>>>(OFF_GIALL, SRCM1, t,
                                                        OFF_GH1, OFF_HCAT, 0);

        // merged launch: z0 = gi2_s, z1 = gh2_s, z2 = gh1_{s+1} (skip on last)
        const dim3& g = (s == NSTEPS - 1) ? gridZ2 : gridZ3;
        gemm_big3_kernel<<<g, blk, SMEM_BIG>>>(
            OFFB_HH, OFFB_HL, OFFB_W2H, OFFB_W2L, bi2, OFF_GI2,
            OFFB_HH + RQ, OFFB_HL + RQ, OFFB_W3H, OFFB_W3L, bh2, OFF_GH2,
            OFFB_HH, OFFB_HL, OFFB_W1H, OFFB_W1L, bh1, OFF_GH1);

        // combine2: h2_s
        gru_combine_kernel<<<combine_blocks, blk>>>(OFF_GI2, 1, 0,
                                                    OFF_GH2, OFF_HCAT + RQ, RQ);

        if (is_dec) {
            // out_t = x_t[:, :H] + [h1|h2] @ Wfc^T + bfc
            const float* resP = (t == 0) ? dec : (out + (size_t)(t - 1) * HQ);
            const int resLd = (t == 0) ? (TGTQ * IQ) : (TGTQ * HQ);
            gemm_bf16x3_kernel<<<gridFC, blk>>>(nullptr, OFF_HCAT, 2 * RQ,
                                                Wfc, bfc,
                                                resP, -1, resLd,
                                                out + (size_t)t * HQ, -1, TGTQ * HQ,
                                                HQ, 2 * RQ,
                                                nullptr, nullptr, -1);
        }
    }
}

// round 17
// speedup vs baseline: 1.0298x; 1.0298x over previous
#include <cuda_runtime.h>
#include <cuda_bf16.h>
#include <cstdint>

// ---------------------------------------------------------------------------
// Problem constants
// ---------------------------------------------------------------------------
#define BQ    4096
#define SRCM1 49
#define TGTQ  25
#define RQ    1024
#define HQ    67
#define IQ    82

// ---------------------------------------------------------------------------
// fp32 scratch
// ---------------------------------------------------------------------------
constexpr long long OFF_HCAT = 0;                                   // [BQ, 2R]
constexpr long long OFF_GI1  = OFF_HCAT + (long long)BQ * 2 * RQ;   // [BQ, 3R] decoder
constexpr long long OFF_GH1  = OFF_GI1  + (long long)BQ * 3 * RQ;
constexpr long long OFF_GI2  = OFF_GH1  + (long long)BQ * 3 * RQ;
constexpr long long OFF_GH2  = OFF_GI2  + (long long)BQ * 3 * RQ;
constexpr long long OFF_GIALL= OFF_GH2  + (long long)BQ * 3 * RQ;   // [BQ*49, 3R]
constexpr long long SCRATCH_TOTAL = OFF_GIALL + (long long)BQ * SRCM1 * 3 * RQ;

__device__ float g_scratch[SCRATCH_TOTAL];

// ---------------------------------------------------------------------------
// bf16 split scratch
// ---------------------------------------------------------------------------
constexpr long long NW = 3LL * RQ * RQ;
constexpr long long OFFB_W1H = 0;                       // Wh1
constexpr long long OFFB_W1L = OFFB_W1H + NW;
constexpr long long OFFB_W2H = OFFB_W1L + NW;           // Wi2
constexpr long long OFFB_W2L = OFFB_W2H + NW;
constexpr long long OFFB_W3H = OFFB_W2L + NW;           // Wh2
constexpr long long OFFB_W3L = OFFB_W3H + NW;
constexpr long long OFFB_HH  = OFFB_W3L + NW;           // hcat hi [BQ][2R]
constexpr long long OFFB_HL  = OFFB_HH + (long long)BQ * 2 * RQ;
constexpr long long BF_TOTAL = OFFB_HL + (long long)BQ * 2 * RQ;

__device__ __nv_bfloat16 g_bf[BF_TOTAL];

// ---------------------------------------------------------------------------
// Common helpers
// ---------------------------------------------------------------------------
__device__ __forceinline__ uint32_t smem_u32(const void* p) {
    uint32_t a;
    asm("{ .reg .u64 t; cvta.to.shared.u64 t, %1; cvt.u32.u64 %0, t; }"
        : "=r"(a) : "l"(p));
    return a;
}

#define MMA_BF16(ACC, A0, A1, A2, A3, B0, B1)                                  \
    asm volatile(                                                              \
        "mma.sync.aligned.m16n8k16.row.col.f32.bf16.bf16.f32 "                 \
        "{%0,%1,%2,%3}, {%4,%5,%6,%7}, {%8,%9}, {%0,%1,%2,%3};"                \
        : "+f"((ACC)[0]), "+f"((ACC)[1]), "+f"((ACC)[2]), "+f"((ACC)[3])       \
        : "r"(A0), "r"(A1), "r"(A2), "r"(A3), "r"(B0), "r"(B1))

#define LDM_X4(R0, R1, R2, R3, ADDR)                                           \
    asm volatile(                                                              \
        "ldmatrix.sync.aligned.m8n8.x4.shared.b16 {%0,%1,%2,%3}, [%4];"        \
        : "=r"(R0), "=r"(R1), "=r"(R2), "=r"(R3) : "r"(ADDR))

__device__ __forceinline__ void cp16(uint32_t dst, const void* src) {
    asm volatile("cp.async.ca.shared.global [%0], [%1], 16;"
                 :: "r"(dst), "l"(src));
}
#define CP_COMMIT() asm volatile("cp.async.commit_group;" ::: "memory")
#define CP_WAIT1()  asm volatile("cp.async.wait_group 1;" ::: "memory")

// Swizzled smem offset inside a 128x16(bf16) tile: row r, 16B-half h.
__device__ __forceinline__ uint32_t swz(int r, int h) {
    return (uint32_t)(((r >> 2) << 7) + ((r & 3) << 5) + ((h ^ ((r >> 2) & 1)) << 4));
}

// ---------------------------------------------------------------------------
// Big GEMM (bf16x3, legacy HMMA):  C[4096, 3072] = A[4096,1024] @ W[3072,1024]^T
//   FROZEN R7/R15 pipeline: 3-stage cp.async ring (48KB static smem),
//   ldmatrix fragments, 128x128 block, 8 warps (2M x 4N), occupancy 2.
//   gridDim.z selects one of THREE fused independent GEMMs
//   (gi2_s, gh2_s, gh1_{s+1}) — merged launch backfills wave tails.
// ---------------------------------------------------------------------------
#define GLDA (2 * RQ)     // 2048
#define GLDC (3 * RQ)     // 3072
#define GKIT 64           // K / 16
#define STG  3

__global__ __launch_bounds__(256, 2)
void gemm_big3_kernel(long long ah0, long long al0, long long wh0, long long wl0,
                      const float* __restrict__ b0, long long c0,
                      long long ah1, long long al1, long long wh1, long long wl1,
                      const float* __restrict__ b1, long long c1,
                      long long ah2, long long al2, long long wh2, long long wl2,
                      const float* __restrict__ b2, long long c2)
{
    __shared__ __align__(128) uint8_t sm[STG * 16384];   // 48KB
    const uint32_t sbase = smem_u32(sm);

    const int z = blockIdx.z;
    const long long ah = (z == 0) ? ah0 : (z == 1) ? ah1 : ah2;
    const long long al = (z == 0) ? al0 : (z == 1) ? al1 : al2;
    const long long wh = (z == 0) ? wh0 : (z == 1) ? wh1 : wh2;
    const long long wl = (z == 0) ? wl0 : (z == 1) ? wl1 : wl2;
    const float* bias  = (z == 0) ? b0  : (z == 1) ? b1  : b2;
    const long long co = (z == 0) ? c0  : (z == 1) ? c1  : c2;

    const __nv_bfloat16* AH = g_bf + ah;
    const __nv_bfloat16* AL = g_bf + al;
    const __nv_bfloat16* WH = g_bf + wh;
    const __nv_bfloat16* WL = g_bf + wl;
    float* C = g_scratch + co;

    const int tid  = threadIdx.x;
    const int lane = tid & 31;
    const int warp = tid >> 5;
    const int wm   = (warp >> 2) * 64;
    const int wn   = (warp & 3) * 32;
    const int bm   = blockIdx.y * 128;
    const int bn   = blockIdx.x * 128;

    // fill coords: row 0..127, 16B half
    const int fr = (tid >> 1) & 127;
    const int fh = tid & 1;
    const uint32_t fd = swz(fr, fh);
    const __nv_bfloat16* pAH = AH + (size_t)(bm + fr) * GLDA + fh * 8;
    const __nv_bfloat16* pAL = AL + (size_t)(bm + fr) * GLDA + fh * 8;
    const __nv_bfloat16* pWH = WH + (size_t)(bn + fr) * RQ + fh * 8;
    const __nv_bfloat16* pWL = WL + (size_t)(bn + fr) * RQ + fh * 8;

    // fragment smem offsets (lane-fixed)
    const int mrow = lane & 15;
    const int akh  = (lane >> 4) & 1;
    uint32_t aoff[4];
#pragma unroll
    for (int mt = 0; mt < 4; mt++) aoff[mt] = swz(wm + mt * 16 + mrow, akh);
    const int nrow = wn + (lane & 7) + ((lane >> 4) & 1) * 8;
    const int bkh  = (lane >> 3) & 1;
    uint32_t boff[2];
#pragma unroll
    for (int p = 0; p < 2; p++) boff[p] = swz(nrow + p * 16, bkh);

    float acc[4][4][4];
#pragma unroll
    for (int mt = 0; mt < 4; mt++)
#pragma unroll
        for (int nt = 0; nt < 4; nt++)
#pragma unroll
            for (int q = 0; q < 4; q++) acc[mt][nt][q] = 0.0f;

    auto fill = [&](int it) {
        if (it < GKIT) {
            const uint32_t bb = sbase + (it % STG) * 16384;
            const int k = it * 16;
            cp16(bb + fd,         pAH + k);
            cp16(bb + 4096 + fd,  pAL + k);
            cp16(bb + 8192 + fd,  pWH + k);
            cp16(bb + 12288 + fd, pWL + k);
        }
        CP_COMMIT();
    };

    fill(0);
    fill(1);

    for (int it = 0; it < GKIT; it++) {
        CP_WAIT1();            // stage it ready (fill it+1 may be in flight)
        __syncthreads();
        fill(it + 2);          // overwrites stage (it-1)%3

        const uint32_t bufb = sbase + (it % STG) * 16384;

        uint32_t bfH[4][2], bfL[4][2];
#pragma unroll
        for (int p = 0; p < 2; p++) {
            uint32_t r0, r1, r2, r3;
            LDM_X4(r0, r1, r2, r3, bufb + 8192 + boff[p]);
            bfH[2 * p][0] = r0; bfH[2 * p][1] = r1;
            bfH[2 * p + 1][0] = r2; bfH[2 * p + 1][1] = r3;
            LDM_X4(r0, r1, r2, r3, bufb + 12288 + boff[p]);
            bfL[2 * p][0] = r0; bfL[2 * p][1] = r1;
            bfL[2 * p + 1][0] = r2; bfL[2 * p + 1][1] = r3;
        }

#pragma unroll
        for (int mt = 0; mt < 4; mt++) {
            uint32_t aH[4], aL[4];
            LDM_X4(aH[0], aH[1], aH[2], aH[3], bufb + aoff[mt]);
            LDM_X4(aL[0], aL[1], aL[2], aL[3], bufb + 4096 + aoff[mt]);
#pragma unroll
            for (int nt = 0; nt < 4; nt++)
                MMA_BF16(acc[mt][nt], aL[0], aL[1], aL[2], aL[3],
                         bfH[nt][0], bfH[nt][1]);
#pragma unroll
            for (int nt = 0; nt < 4; nt++)
                MMA_BF16(acc[mt][nt], aH[0], aH[1], aH[2], aH[3],
                         bfL[nt][0], bfL[nt][1]);
#pragma unroll
            for (int nt = 0; nt < 4; nt++)
                MMA_BF16(acc[mt][nt], aH[0], aH[1], aH[2], aH[3],
                         bfH[nt][0], bfH[nt][1]);
        }
    }

    // epilogue: bias, float2 stores
#pragma unroll
    for (int mt = 0; mt < 4; mt++) {
#pragma unroll
        for (int nt = 0; nt < 4; nt++) {
            const int n = bn + wn + nt * 8 + 2 * (lane & 3);
            const float b0v = bias[n], b1v = bias[n + 1];
#pragma unroll
            for (int h = 0; h < 2; h++) {
                const int m = bm + wm + mt * 16 + (lane >> 2) + h * 8;
                float2 v;
                v.x = acc[mt][nt][h * 2 + 0] + b0v;
                v.y = acc[mt][nt][h * 2 + 1] + b1v;
                *(float2*)(C + (size_t)m * GLDC + n) = v;
            }
        }
    }
}

// ---------------------------------------------------------------------------
// Legacy bf16x3 mma.sync GEMM (fp32 inputs): K=82 input GEMMs and N=67 FC.
//   xt >= 0: A is the decoder input x_t gathered on the fly.
//   resExt: external residual base (row stride res_ld) when Roff < 0.
// ---------------------------------------------------------------------------
#define BM 128
#define BN 64
#define BK 32

__device__ __forceinline__ void split2(float x, float y, uint32_t& hi, uint32_t& lo)
{
    __nv_bfloat162 h = __floats2bfloat162_rn(x, y);
    float xr = x - __bfloat162float(__low2bfloat16(h));
    float yr = y - __bfloat162float(__high2bfloat16(h));
    __nv_bfloat162 l = __floats2bfloat162_rn(xr, yr);
    hi = *reinterpret_cast<uint32_t*>(&h);
    lo = *reinterpret_cast<uint32_t*>(&l);
}

__global__ __launch_bounds__(256, 2)
void gemm_bf16x3_kernel(const float* __restrict__ Aext, long long Aoff, int lda,
                        const float* __restrict__ W,
                        const float* __restrict__ bias,
                        const float* __restrict__ resExt, long long Roff, int res_ld,
                        float* __restrict__ Cext, long long Coff, int ldc,
                        int N, int K,
                        const float* __restrict__ decP,
                        const float* __restrict__ outP, int xt)
{
    const float* A = (Aoff >= 0) ? (g_scratch + Aoff) : Aext;
    float*       C = (Coff >= 0) ? (g_scratch + Coff) : Cext;
    const float* res = (Roff >= 0) ? (g_scratch + Roff) : resExt;

    __shared__ uint32_t AsH[BK / 2][BM + 8];
    __shared__ uint32_t AsL[BK / 2][BM + 8];
    __shared__ uint32_t BsH[BK / 2][BN + 8];
    __shared__ uint32_t BsL[BK / 2][BN + 8];

    const int tid  = threadIdx.x;
    const int bm   = blockIdx.y * BM;
    const int bn   = blockIdx.x * BN;
    const int arow = tid >> 1;
    const int akh  = (tid & 1) * 16;
    const int wrow = tid >> 2;
    const int wkq  = (tid & 3) * 8;
    const int lane = tid & 31;
    const int warp = tid >> 5;
    const int wm   = (warp >> 1) * 32;
    const int wn   = (warp & 1) * 32;
    const int gid  = lane >> 2;
    const int tig  = lane & 3;

    const bool fast   = (xt < 0) && ((K & (BK - 1)) == 0) && ((lda & 3) == 0);
    const int  ktiles = (K + BK - 1) / BK;

    float acc[2][4][4];
#pragma unroll
    for (int mt = 0; mt < 2; mt++)
#pragma unroll
        for (int nt = 0; nt < 4; nt++)
#pragma unroll
            for (int q = 0; q < 4; q++) acc[mt][nt][q] = 0.0f;

    for (int kt = 0; kt < ktiles; kt++) {
        const int k0 = kt * BK;
        __syncthreads();

        float av[16];
        if (fast) {
#pragma unroll
            for (int q = 0; q < 4; q++) {
                const float4 v = *reinterpret_cast<const float4*>(
                    A + (size_t)(bm + arow) * lda + k0 + akh + q * 4);
                av[q * 4 + 0] = v.x; av[q * 4 + 1] = v.y;
                av[q * 4 + 2] = v.z; av[q * 4 + 3] = v.w;
            }
        } else if (xt >= 0) {
            // on-the-fly decoder input gather (replaces build_x + X buffer)
            const int m = bm + arow;
#pragma unroll
            for (int j = 0; j < 16; j++) {
                const int k = k0 + akh + j;
                float v = 0.0f;
                if (k < K) {
                    if (xt == 0)
                        v = decP[(size_t)m * TGTQ * IQ + k];
                    else if (k < HQ)
                        v = outP[((size_t)m * TGTQ + (xt - 1)) * HQ + k];
                    else
                        v = decP[((size_t)m * TGTQ + xt) * IQ + k];
                }
                av[j] = v;
            }
        } else {
#pragma unroll
            for (int j = 0; j < 16; j++) {
                const int k = k0 + akh + j;
                av[j] = (k < K) ? A[(size_t)(bm + arow) * lda + k] : 0.0f;
            }
        }
#pragma unroll
        for (int j = 0; j < 8; j++) {
            uint32_t hi, lo;
            split2(av[2 * j], av[2 * j + 1], hi, lo);
            AsH[akh / 2 + j][arow] = hi;
            AsL[akh / 2 + j][arow] = lo;
        }

        float wv[8];
        if (((K & (BK - 1)) == 0) && (bn + wrow) < N) {
#pragma unroll
            for (int q = 0; q < 2; q++) {
                const float4 v = *reinterpret_cast<const float4*>(
                    W + (size_t)(bn + wrow) * K + k0 + wkq + q * 4);
                wv[q * 4 + 0] = v.x; wv[q * 4 + 1] = v.y;
                wv[q * 4 + 2] = v.z; wv[q * 4 + 3] = v.w;
            }
        } else {
#pragma unroll
            for (int j = 0; j < 8; j++) {
                const int k = k0 + wkq + j;
                wv[j] = (k < K && (bn + wrow) < N)
                    ? W[(size_t)(bn + wrow) * K + k] : 0.0f;
            }
        }
#pragma unroll
        for (int j = 0; j < 4; j++) {
            uint32_t hi, lo;
            split2(wv[2 * j], wv[2 * j + 1], hi, lo);
            BsH[wkq / 2 + j][wrow] = hi;
            BsL[wkq / 2 + j][wrow] = lo;
        }
        __syncthreads();

#pragma unroll
        for (int kc = 0; kc < 2; kc++) {
            const int kb = kc * 8;
            uint32_t afH[2][4], afL[2][4], bfH[4][2], bfL[4][2];
#pragma unroll
            for (int mt = 0; mt < 2; mt++) {
                const int r0 = wm + mt * 16 + gid;
                afH[mt][0] = AsH[kb + tig][r0];
                afH[mt][1] = AsH[kb + tig][r0 + 8];
                afH[mt][2] = AsH[kb + tig + 4][r0];
                afH[mt][3] = AsH[kb + tig + 4][r0 + 8];
                afL[mt][0] = AsL[kb + tig][r0];
                afL[mt][1] = AsL[kb + tig][r0 + 8];
                afL[mt][2] = AsL[kb + tig + 4][r0];
                afL[mt][3] = AsL[kb + tig + 4][r0 + 8];
            }
#pragma unroll
            for (int nt = 0; nt < 4; nt++) {
                const int c0 = wn + nt * 8 + gid;
                bfH[nt][0] = BsH[kb + tig][c0];
                bfH[nt][1] = BsH[kb + tig + 4][c0];
                bfL[nt][0] = BsL[kb + tig][c0];
                bfL[nt][1] = BsL[kb + tig + 4][c0];
            }
#pragma unroll
            for (int mt = 0; mt < 2; mt++)
#pragma unroll
                for (int nt = 0; nt < 4; nt++) {
                    MMA_BF16(acc[mt][nt],
                             afL[mt][0], afL[mt][1], afL[mt][2], afL[mt][3],
                             bfH[nt][0], bfH[nt][1]);
                    MMA_BF16(acc[mt][nt],
                             afH[mt][0], afH[mt][1], afH[mt][2], afH[mt][3],
                             bfL[nt][0], bfL[nt][1]);
                    MMA_BF16(acc[mt][nt],
                             afH[mt][0], afH[mt][1], afH[mt][2], afH[mt][3],
                             bfH[nt][0], bfH[nt][1]);
                }
        }
    }

#pragma unroll
    for (int mt = 0; mt < 2; mt++) {
#pragma unroll
        for (int nt = 0; nt < 4; nt++) {
            const int m0 = bm + wm + mt * 16 + gid;
            const int n0 = bn + wn + nt * 8 + 2 * tig;
#pragma unroll
            for (int h = 0; h < 2; h++) {
                const int m = m0 + h * 8;
#pragma unroll
                for (int q = 0; q < 2; q++) {
                    const int n = n0 + q;
                    if (n < N) {
                        float v = acc[mt][nt][h * 2 + q] + bias[n];
                        if (res) v += res[(size_t)m * res_ld + n];
                        C[(size_t)m * ldc + n] = v;
                    }
                }
            }
        }
    }
}

// ---------------------------------------------------------------------------
// GRU combine body (vectorized x4), shared by single and dual variants.
//   bh_direct non-null: gh gates are bh[j] broadcast (h_prev == 0 step).
// ---------------------------------------------------------------------------
__device__ __forceinline__ void gru_body(int idx4,
                                         long long gi_off, int gi_rstride, int gi_roff,
                                         long long gh_off, const float* bh_direct,
                                         long long h_off, long long hb)
{
    const int b  = idx4 >> 8;            // / (RQ/4)
    const int j4 = (idx4 & 255) * 4;

    const float* gi = g_scratch + gi_off;
    float*       h  = g_scratch + h_off;

    const size_t gr = ((size_t)b * gi_rstride + gi_roff) * (3 * RQ) + j4;
    const float4 ir4 = *(const float4*)(gi + gr);
    const float4 iz4 = *(const float4*)(gi + gr + RQ);
    const float4 in4 = *(const float4*)(gi + gr + 2 * RQ);

    float4 hr4, hz4, hn4;
    if (bh_direct) {
        hr4 = *(const float4*)(bh_direct + j4);
        hz4 = *(const float4*)(bh_direct + RQ + j4);
        hn4 = *(const float4*)(bh_direct + 2 * RQ + j4);
    } else {
        const float* gh = g_scratch + gh_off;
        const size_t g = (size_t)b * 3 * RQ + j4;
        hr4 = *(const float4*)(gh + g);
        hz4 = *(const float4*)(gh + g + RQ);
        hn4 = *(const float4*)(gh + g + 2 * RQ);
    }

    const size_t hi = (size_t)b * 2 * RQ + j4;
    const float4 hp4 = *(const float4*)(h + hi);

    const float ir[4] = {ir4.x, ir4.y, ir4.z, ir4.w};
    const float iz[4] = {iz4.x, iz4.y, iz4.z, iz4.w};
    const float in_[4] = {in4.x, in4.y, in4.z, in4.w};
    const float hr[4] = {hr4.x, hr4.y, hr4.z, hr4.w};
    const float hz[4] = {hz4.x, hz4.y, hz4.z, hz4.w};
    const float hn[4] = {hn4.x, hn4.y, hn4.z, hn4.w};
    const float hp[4] = {hp4.x, hp4.y, hp4.z, hp4.w};

    float v[4];
    __nv_bfloat16 vh[4], vl[4];
#pragma unroll
    for (int q = 0; q < 4; q++) {
        const float r = 1.0f / (1.0f + expf(-(ir[q] + hr[q])));
        const float z = 1.0f / (1.0f + expf(-(iz[q] + hz[q])));
        const float n = tanhf(in_[q] + r * hn[q]);
        v[q] = (1.0f - z) * n + z * hp[q];
        vh[q] = __float2bfloat16(v[q]);
        vl[q] = __float2bfloat16(v[q] - __bfloat162float(vh[q]));
    }

    *(float4*)(h + hi) = make_float4(v[0], v[1], v[2], v[3]);

    const size_t bo = (size_t)b * 2 * RQ + hb + j4;
    __nv_bfloat162* pH = (__nv_bfloat162*)(g_bf + OFFB_HH + bo);
    __nv_bfloat162* pL = (__nv_bfloat162*)(g_bf + OFFB_HL + bo);
    pH[0] = __nv_bfloat162(vh[0], vh[1]);
    pH[1] = __nv_bfloat162(vh[2], vh[3]);
    pL[0] = __nv_bfloat162(vl[0], vl[1]);
    pL[1] = __nv_bfloat162(vl[2], vl[3]);
}

__global__ void gru_combine_kernel(long long gi_off, int gi_rstride, int gi_roff,
                                   long long gh_off, const float* bh_direct,
                                   long long h_off, long long hb)
{
    const int idx4 = blockIdx.x * blockDim.x + threadIdx.x;
    if (idx4 >= BQ * RQ / 4) return;
    gru_body(idx4, gi_off, gi_rstride, gi_roff, gh_off, bh_direct, h_off, hb);
}

// Fused pair: set A = combine2_{s-1} (layer 2), set B = combine1_s (layer 1).
// Both depend only on the previous z3 launch; writes are disjoint.
__global__ void gru_combine2x_kernel(long long giA, int strA, int roffA,
                                     long long ghA, long long hA, long long hbA,
                                     long long giB, int strB, int roffB,
                                     long long ghB, long long hB, long long hbB)
{
    const int gidx = blockIdx.x * blockDim.x + threadIdx.x;
    const int half = BQ * RQ / 4;
    if (gidx < half)
        gru_body(gidx, giA, strA, roffA, ghA, nullptr, hA, hbA);
    else if (gidx < 2 * half)
        gru_body(gidx - half, giB, strB, roffB, ghB, nullptr, hB, hbB);
}

// ---------------------------------------------------------------------------
// Weight split, zero fills
// ---------------------------------------------------------------------------
__global__ void split_w_kernel(const float* __restrict__ W,
                               long long dh, long long dl, int count)
{
    const int i = blockIdx.x * blockDim.x + threadIdx.x;
    if (i >= count) return;
    const float v = W[i];
    const __nv_bfloat16 h = __float2bfloat16(v);
    g_bf[dh + i] = h;
    g_bf[dl + i] = __float2bfloat16(v - __bfloat162float(h));
}

__global__ void zero_kernel(long long off, long long count)
{
    const long long idx = (long long)blockIdx.x * blockDim.x + threadIdx.x;
    if (idx < count) g_scratch[off + idx] = 0.0f;
}

__global__ void zero_bf_kernel(long long off, long long count)
{
    const long long idx = (long long)blockIdx.x * blockDim.x + threadIdx.x;
    if (idx < count) g_bf[off + idx] = __float2bfloat16(0.0f);
}

// ---------------------------------------------------------------------------
// Launch
// ---------------------------------------------------------------------------
extern "C" void kernel_launch(void* const* d_in, const int* in_sizes, int n_in,
                              void* d_out, int out_size)
{
    const float* enc = (const float*)d_in[0];
    const float* dec = (const float*)d_in[1];
    const float* Wi1 = (const float*)d_in[2];
    const float* Wh1 = (const float*)d_in[3];
    const float* bi1 = (const float*)d_in[4];
    const float* bh1 = (const float*)d_in[5];
    const float* Wi2 = (const float*)d_in[6];
    const float* Wh2 = (const float*)d_in[7];
    const float* bi2 = (const float*)d_in[8];
    const float* bh2 = (const float*)d_in[9];
    const float* Wfc = (const float*)d_in[10];
    const float* bfc = (const float*)d_in[11];
    float* out = (float*)d_out;
    (void)in_sizes; (void)n_in; (void)out_size;

    const dim3 blk(256);
    const dim3 gridZ2(GLDC / 128, BQ / 128, 2);            // (24, 32, 2)
    const dim3 gridZ3(GLDC / 128, BQ / 128, 3);            // (24, 32, 3)
    const dim3 grid3R((3 * RQ) / BN, BQ / BM);             // (48, 32)
    const dim3 gridEnc((3 * RQ) / BN, (BQ * SRCM1) / BM);  // (48, 1568)
    const dim3 gridFC((HQ + BN - 1) / BN, BQ / BM);        // (2, 32)
    const int  combine_blocks = (BQ * RQ / 4) / 256;       // 4096
    const int  wsplit_blocks = (int)((NW + 255) / 256);

    // per-launch init: zero h (fp32 + splits), split weights
    zero_kernel<<<(int)((BQ * 2LL * RQ + 255) / 256), blk>>>(OFF_HCAT, (long long)BQ * 2 * RQ);
    zero_bf_kernel<<<(int)((2LL * BQ * 2 * RQ + 255) / 256), blk>>>(OFFB_HH, 2LL * BQ * 2 * RQ);
    split_w_kernel<<<wsplit_blocks, blk>>>(Wh1, OFFB_W1H, OFFB_W1L, (int)NW);
    split_w_kernel<<<wsplit_blocks, blk>>>(Wi2, OFFB_W2H, OFFB_W2L, (int)NW);
    split_w_kernel<<<wsplit_blocks, blk>>>(Wh2, OFFB_W3H, OFFB_W3L, (int)NW);

    // batched encoder gi1: enc flattened row-major [BQ*49, IQ], row m = b*49+t
    gemm_bf16x3_kernel<<<gridEnc, blk>>>(enc, -1, IQ,
                                         Wi1, bi1,
                                         nullptr, -1, 0,
                                         nullptr, OFF_GIALL, 3 * RQ, 3 * RQ, IQ,
                                         nullptr, nullptr, -1);

    const int NSTEPS = SRCM1 + TGTQ;    // 74

    // ---------------- encoder: combine-pair fused schedule ----------------
    for (int s = 0; s < SRCM1; s++) {
        if (s == 0) {
            // h1 == 0 -> gh1_0 == bh1 (direct); no prologue GEMM needed
            gru_combine_kernel<<<combine_blocks, blk>>>(OFF_GIALL, SRCM1, 0,
                                                        0, bh1, OFF_HCAT, 0);
        } else {
            // fused: combine2_{s-1} (layer2) + combine1_s (layer1)
            gru_combine2x_kernel<<<2 * combine_blocks, blk>>>(
                OFF_GI2, 1, 0, OFF_GH2, OFF_HCAT + RQ, RQ,
                OFF_GIALL, SRCM1, s, OFF_GH1, OFF_HCAT, 0);
        }
        // merged z3: z0 = gi2_s, z1 = gh2_s, z2 = gh1_{s+1}
        gemm_big3_kernel<<<gridZ3, blk>>>(
            OFFB_HH, OFFB_HL, OFFB_W2H, OFFB_W2L, bi2, OFF_GI2,
            OFFB_HH + RQ, OFFB_HL + RQ, OFFB_W3H, OFFB_W3L, bh2, OFF_GH2,
            OFFB_HH, OFFB_HL, OFFB_W1H, OFFB_W1L, bh1, OFF_GH1);
    }
    // last encoder combine2 (s = SRCM1-1) runs standalone
    gru_combine_kernel<<<combine_blocks, blk>>>(OFF_GI2, 1, 0,
                                                OFF_GH2, nullptr, OFF_HCAT + RQ, RQ);

    // ---------------- decoder: 25 steps (serial chain forces R15 order) ---
    for (int t = 0; t < TGTQ; t++) {
        const int s = SRCM1 + t;
        // gi1 with fused on-the-fly input gather
        gemm_bf16x3_kernel<<<grid3R, blk>>>(nullptr, -1, 0,
                                            Wi1, bi1,
                                            nullptr, -1, 0,
                                            nullptr, OFF_GI1, 3 * RQ, 3 * RQ, IQ,
                                            dec, out, t);
        gru_combine_kernel<<<combine_blocks, blk>>>(OFF_GI1, 1, 0,
                                                    OFF_GH1, nullptr, OFF_HCAT, 0);

        const dim3& g = (s == NSTEPS - 1) ? gridZ2 : gridZ3;
        gemm_big3_kernel<<<g, blk>>>(
            OFFB_HH, OFFB_HL, OFFB_W2H, OFFB_W2L, bi2, OFF_GI2,
            OFFB_HH + RQ, OFFB_HL + RQ, OFFB_W3H, OFFB_W3L, bh2, OFF_GH2,
            OFFB_HH, OFFB_HL, OFFB_W1H, OFFB_W1L, bh1, OFF_GH1);

        gru_combine_kernel<<<combine_blocks, blk>>>(OFF_GI2, 1, 0,
                                                    OFF_GH2, nullptr, OFF_HCAT + RQ, RQ);

        // out_t = x_t[:, :H] + [h1|h2] @ Wfc^T + bfc
        const float* resP = (t == 0) ? dec : (out + (size_t)(t - 1) * HQ);
        const int resLd = (t == 0) ? (TGTQ * IQ) : (TGTQ * HQ);
        gemm_bf16x3_kernel<<<gridFC, blk>>>(nullptr, OFF_HCAT, 2 * RQ,
                                            Wfc, bfc,
                                            resP, -1, resLd,
                                            out + (size_t)t * HQ, -1, TGTQ * HQ,
                                            HQ, 2 * RQ,
                                            nullptr, nullptr, -1);
    }
}